// round 5
// baseline (speedup 1.0000x reference)
#include <cuda_runtime.h>
#include <math.h>
#include <stdint.h>

#define NTOK 8192
#define QS 288            // qkv row stride: 256 v | 8 qdot | 8 kdot | pad
#define ES 132            // edge smem row stride (floats)
#define HXS 1280          // hx row stride: 256 scalar ctx | 1024 ew

// ---------------- device scratch ----------------
__device__ float g_qkv[NTOK*QS];
__device__ float g_hx[NTOK*HXS];
__device__ float g_hmid[NTOK*256];
__device__ float g_gate[NTOK];
__device__ float g_proj[NTOK*3];
__device__ float g_center[16*3];
__device__ float g_V[16*9];
__device__ float g_Wcomb[256*QS];
__device__ float g_bcomb[QS];
__device__ float g_weff[128*8];
__device__ float g_beff[8];
__device__ float g_W1[HXS*256];     // folded fc1 weight: [1280, 256]
__device__ float g_b1[256];         // folded fc1 bias

__device__ __forceinline__ float siluf(float x){ return x/(1.f+__expf(-x)); }
__device__ __forceinline__ uint32_t f2tf32(float x){
    uint32_t u; asm("cvt.rna.tf32.f32 %0, %1;" : "=r"(u) : "f"(x)); return u;
}
__device__ __forceinline__ float tf32f(float x){ return __uint_as_float(f2tf32(x)); }

// ---------------- prep: fold effective weights ----------------
__global__ void prep_kernel(const float* __restrict__ W_qkv, const float* __restrict__ b_qkv,
                            const float* __restrict__ w_attn,
                            const float* __restrict__ W_qkv_e, const float* __restrict__ b_qkv_e,
                            const float* __restrict__ w_edge,
                            const float* __restrict__ W_fc1, const float* __restrict__ b_fc1)
{
    int gid = blockIdx.x*blockDim.x + threadIdx.x;
    int gstride = gridDim.x*blockDim.x;
    // Wcomb [256, QS]
    for (int idx = gid; idx < 256*QS; idx += gstride) {
        int c = idx / QS, j = idx - c*QS;
        float w = 0.f;
        if (j < 256) {
            w = W_qkv[c*768 + 512 + j];
        } else if (j < 264) {
            int h = j - 256; float s = 0.f;
            #pragma unroll
            for (int d = 0; d < 32; d++) s += W_qkv[c*768 + h*32 + d]*w_attn[d];
            w = s;
        } else if (j < 272) {
            int h = j - 264; float s = 0.f;
            #pragma unroll
            for (int d = 0; d < 32; d++) s += W_qkv[c*768 + 256 + h*32 + d]*w_attn[d];
            w = s;
        }
        g_Wcomb[idx] = w;
    }
    // W1 [1280, 256]: rows 0..255 = W_fc1[0:256]; rows 256.. = fold(Wve, W1b)
    for (int idx = gid; idx < HXS*256; idx += gstride) {
        int j = idx >> 8, o = idx & 255;
        float w;
        if (j < 256) {
            w = W_fc1[j*256 + o];
        } else {
            int hc = j - 256, h = hc >> 7, c = hc & 127;
            float s = 0.f;
            #pragma unroll
            for (int jp = 0; jp < 16; jp++)
                s += W_qkv_e[c*256 + 128 + h*16 + jp]*W_fc1[(256 + h*16 + jp)*256 + o];
            w = s;
        }
        g_W1[idx] = w;
    }
    if (blockIdx.x == 0) {
        for (int j = threadIdx.x; j < QS; j += blockDim.x) {
            float bv = 0.f;
            if (j < 256) bv = b_qkv[512 + j];
            else if (j < 264) { int h = j-256; for (int d=0; d<32; d++) bv += b_qkv[h*32+d]*w_attn[d]; }
            else if (j < 272) { int h = j-264; for (int d=0; d<32; d++) bv += b_qkv[256 + h*32+d]*w_attn[d]; }
            g_bcomb[j] = bv;
        }
    }
    if (blockIdx.x == 1) {
        for (int idx = threadIdx.x; idx < 128*8; idx += blockDim.x) {
            int c = idx >> 3, h = idx & 7; float s = 0.f;
            #pragma unroll
            for (int e = 0; e < 16; e++) s += W_qkv_e[c*256 + h*16 + e]*w_edge[e];
            g_weff[idx] = s;
        }
        if (threadIdx.x < 8) {
            float s = 0.f;
            for (int e = 0; e < 16; e++) s += b_qkv_e[threadIdx.x*16 + e]*w_edge[e];
            g_beff[threadIdx.x] = s;
        }
    }
    if (blockIdx.x == 2 && threadIdx.x < 256) {
        int o = threadIdx.x;
        float s = b_fc1[o];
        for (int j = 0; j < 128; j++)
            s += b_qkv_e[128 + j]*W_fc1[(256 + j)*256 + o];
        g_b1[o] = s;
    }
}

// ---------------- per-graph geometry ----------------
__device__ void jacobi3(double a00,double a01,double a02,double a11,double a12,double a22,
                        double V[3][3])
{
    double A[3][3] = {{a00,a01,a02},{a01,a11,a12},{a02,a12,a22}};
    V[0][0]=1; V[0][1]=0; V[0][2]=0;
    V[1][0]=0; V[1][1]=1; V[1][2]=0;
    V[2][0]=0; V[2][1]=0; V[2][2]=1;
    for (int it = 0; it < 60; ++it) {
        int p = 0, q = 1; double mx = fabs(A[0][1]);
        if (fabs(A[0][2]) > mx) { mx = fabs(A[0][2]); p = 0; q = 2; }
        if (fabs(A[1][2]) > mx) { mx = fabs(A[1][2]); p = 1; q = 2; }
        if (mx <= 1e-13*(fabs(A[0][0])+fabs(A[1][1])+fabs(A[2][2]))) break;
        double apq = A[p][q];
        double theta = (A[q][q]-A[p][p])/(2.0*apq);
        double t = 1.0/(fabs(theta)+sqrt(theta*theta+1.0));
        if (theta < 0) t = -t;
        double c = 1.0/sqrt(t*t+1.0), s = t*c;
        for (int k = 0; k < 3; k++) { double akp=A[k][p], akq=A[k][q]; A[k][p]=c*akp-s*akq; A[k][q]=s*akp+c*akq; }
        for (int k = 0; k < 3; k++) { double apk=A[p][k], aqk=A[q][k]; A[p][k]=c*apk-s*aqk; A[q][k]=s*apk+c*aqk; }
        for (int k = 0; k < 3; k++) { double vkp=V[k][p], vkq=V[k][q]; V[k][p]=c*vkp-s*vkq; V[k][q]=s*vkp+c*vkq; }
    }
}

__global__ void geom_kernel(const float* __restrict__ geo)
{
    __shared__ double sred[8][9];
    __shared__ double sCd[3];
    __shared__ float sV[9], sC[3];
    int b = blockIdx.x, tid = threadIdx.x, lane = tid & 31, warp = tid >> 5;
    const float* G = geo + (size_t)b*512*3;

    {
        double s[3] = {0,0,0};
        for (int p = tid; p < 512; p += 256) { s[0] += G[p*3]; s[1] += G[p*3+1]; s[2] += G[p*3+2]; }
        #pragma unroll
        for (int k = 0; k < 3; k++)
            #pragma unroll
            for (int o = 16; o; o >>= 1) s[k] += __shfl_xor_sync(0xffffffffu, s[k], o);
        if (lane == 0) { sred[warp][0]=s[0]; sred[warp][1]=s[1]; sred[warp][2]=s[2]; }
    }
    __syncthreads();
    if (tid == 0) {
        for (int k = 0; k < 3; k++) {
            double t = 0; for (int w = 0; w < 8; w++) t += sred[w][k];
            sCd[k] = t/512.0;
        }
    }
    __syncthreads();
    double c0 = sCd[0], c1 = sCd[1], c2 = sCd[2];

    {
        double m[6] = {0,0,0,0,0,0};
        for (int p = tid; p < 512; p += 256) {
            double dx = G[p*3]-c0, dy = G[p*3+1]-c1, dz = G[p*3+2]-c2;
            m[0] += dx*dx; m[1] += dx*dy; m[2] += dx*dz;
            m[3] += dy*dy; m[4] += dy*dz; m[5] += dz*dz;
        }
        #pragma unroll
        for (int k = 0; k < 6; k++)
            #pragma unroll
            for (int o = 16; o; o >>= 1) m[k] += __shfl_xor_sync(0xffffffffu, m[k], o);
        if (lane == 0) for (int k = 0; k < 6; k++) sred[warp][k] = m[k];
    }
    __syncthreads();
    if (tid == 0) {
        double m[6];
        for (int k = 0; k < 6; k++) { double t=0; for (int w=0; w<8; w++) t += sred[w][k]; m[k]=t; }
        double V[3][3];
        jacobi3(m[0],m[1],m[2],m[3],m[4],m[5], V);
        for (int i = 0; i < 3; i++)
            for (int j = 0; j < 3; j++) { sV[i*3+j] = (float)V[i][j]; g_V[b*9+i*3+j] = (float)V[i][j]; }
        sC[0]=(float)c0; sC[1]=(float)c1; sC[2]=(float)c2;
        g_center[b*3+0]=(float)c0; g_center[b*3+1]=(float)c1; g_center[b*3+2]=(float)c2;
    }
    __syncthreads();

    for (int p = tid; p < 512; p += 256) {
        int t = b*512 + p;
        float dx = G[p*3]-sC[0], dy = G[p*3+1]-sC[1], dz = G[p*3+2]-sC[2];
        for (int d = 0; d < 3; d++)
            g_proj[t*3+d] = dx*sV[0*3+d] + dy*sV[1*3+d] + dz*sV[2*3+d];
    }
}

// ---------------- qkv GEMM: full-K A resident + LN + gate, B reg-prefetch ----------------
// K=256, N=288. 256 threads, 8 warps = 2x4.
__global__ __launch_bounds__(256)
void gemm_qkv(const float* __restrict__ A, const float* __restrict__ Bw,
              const float* __restrict__ bias, float* __restrict__ C,
              const float* __restrict__ Wg, const float* __restrict__ bg,
              const float* __restrict__ lng, const float* __restrict__ lnb)
{
    constexpr int K = 256, N = QS;
    constexpr int SA = 292, BS = 292;
    constexpr int WN = N/4, NT = WN/8, CT = N/32, KT = K/32;
    extern __shared__ float smem[];
    float* sA = smem;              // [32][SA]
    float* sB = smem + 32*SA;      // [32][BS]
    const int tid = threadIdx.x, lane = tid & 31, warp = tid >> 5;
    const int wr = warp >> 2, wc = warp & 3;
    const int gid = lane >> 2, tig = lane & 3;
    const int rowBase = blockIdx.x*32;

    // load A [32,256]
    for (int i = tid; i < 32*64; i += 256) {
        int r = i >> 6, c4 = i & 63;
        *(float4*)&sA[r*SA + c4*4] = *(const float4*)&A[(size_t)(rowBase + r)*K + c4*4];
    }
    __syncthreads();
    // LN rows + gate, write tf32-rounded values back
    #pragma unroll
    for (int rr = 0; rr < 4; rr++) {
        int row = warp*4 + rr;
        float v[8]; float s = 0.f, s2 = 0.f, gd = 0.f;
        #pragma unroll
        for (int j = 0; j < 8; j++) {
            int c = lane + 32*j;
            float t = sA[row*SA + c];
            v[j] = t; s += t; s2 += t*t; gd += t*Wg[c];
        }
        #pragma unroll
        for (int o = 16; o; o >>= 1) {
            s  += __shfl_xor_sync(0xffffffffu, s,  o);
            s2 += __shfl_xor_sync(0xffffffffu, s2, o);
            gd += __shfl_xor_sync(0xffffffffu, gd, o);
        }
        float mean = s*(1.f/256.f);
        float rstd = rsqrtf(s2*(1.f/256.f) - mean*mean + 1e-5f);
        #pragma unroll
        for (int j = 0; j < 8; j++) {
            int c = lane + 32*j;
            sA[row*SA + c] = tf32f((v[j]-mean)*rstd*lng[c] + lnb[c]);
        }
        if (lane == 0) g_gate[rowBase + row] = 1.f/(1.f + __expf(-(gd + bg[0])));
    }

    float acc[NT][4];
    #pragma unroll
    for (int t = 0; t < NT; t++) {
        int j0 = wc*WN + t*8 + tig*2;
        acc[t][0] = bias[j0];   acc[t][1] = bias[j0+1];
        acc[t][2] = bias[j0];   acc[t][3] = bias[j0+1];
    }

    // B prefetch: per kt, 32*288 floats /256 = 36 floats = 9 float4 per thread
    float4 rB[9];
    {
        #pragma unroll
        for (int jj = 0; jj < 9; jj++) {
            int idx = tid + 256*jj;
            int r = idx/72, c4 = idx - r*72;
            rB[jj] = *(const float4*)&Bw[(size_t)r*N + c4*4];
        }
    }
    for (int kt = 0; kt < KT; ++kt) {
        __syncthreads();
        #pragma unroll
        for (int jj = 0; jj < 9; jj++) {
            int idx = tid + 256*jj;
            int r = idx/72, c4 = idx - r*72;
            float* d = &sB[r*BS + c4*4];
            d[0] = tf32f(rB[jj].x); d[1] = tf32f(rB[jj].y);
            d[2] = tf32f(rB[jj].z); d[3] = tf32f(rB[jj].w);
        }
        __syncthreads();
        if (kt + 1 < KT) {
            #pragma unroll
            for (int jj = 0; jj < 9; jj++) {
                int idx = tid + 256*jj;
                int r = idx/72, c4 = idx - r*72;
                rB[jj] = *(const float4*)&Bw[(size_t)((kt+1)*32 + r)*N + c4*4];
            }
        }
        #pragma unroll
        for (int kk = 0; kk < 4; kk++) {
            int kc = kt*32 + kk*8;
            uint32_t a0 = __float_as_uint(sA[(wr*16 + gid    )*SA + kc + tig    ]);
            uint32_t a1 = __float_as_uint(sA[(wr*16 + gid + 8)*SA + kc + tig    ]);
            uint32_t a2 = __float_as_uint(sA[(wr*16 + gid    )*SA + kc + tig + 4]);
            uint32_t a3 = __float_as_uint(sA[(wr*16 + gid + 8)*SA + kc + tig + 4]);
            #pragma unroll
            for (int t = 0; t < NT; t++) {
                int n0 = wc*WN + t*8;
                uint32_t b0 = __float_as_uint(sB[(kk*8 + tig    )*BS + n0 + gid]);
                uint32_t b1 = __float_as_uint(sB[(kk*8 + tig + 4)*BS + n0 + gid]);
                asm volatile(
                    "mma.sync.aligned.m16n8k8.row.col.f32.tf32.tf32.f32 "
                    "{%0,%1,%2,%3}, {%4,%5,%6,%7}, {%8,%9}, {%0,%1,%2,%3};"
                    : "+f"(acc[t][0]), "+f"(acc[t][1]), "+f"(acc[t][2]), "+f"(acc[t][3])
                    : "r"(a0), "r"(a1), "r"(a2), "r"(a3), "r"(b0), "r"(b1));
            }
        }
    }

    __syncthreads();
    #pragma unroll
    for (int t = 0; t < NT; t++) {
        int n0 = wc*WN + t*8 + tig*2;
        int r0 = wr*16 + gid;
        sA[ r0     *SA + n0    ] = acc[t][0];
        sA[ r0     *SA + n0 + 1] = acc[t][1];
        sA[(r0 + 8)*SA + n0    ] = acc[t][2];
        sA[(r0 + 8)*SA + n0 + 1] = acc[t][3];
    }
    __syncthreads();
    #pragma unroll
    for (int rr = 0; rr < 4; rr++) {
        int row = warp*4 + rr;
        int grow = rowBase + row;
        #pragma unroll
        for (int j = 0; j < CT; j++) {
            int col = lane + 32*j;
            C[(size_t)grow*N + col] = sA[row*SA + col];
        }
    }
}

// ---------------- K-tiled tf32 GEMM with reg-prefetch double buffering ----------------
// EPI: 1 = gelu+LN, 2 = +residual. N=256. LDA = K.
template<int K, int EPI>
__global__ __launch_bounds__(256)
void gemm_kt(const float* __restrict__ A, const float* __restrict__ Bw,
             const float* __restrict__ bias, float* __restrict__ C,
             const float* __restrict__ p1, const float* __restrict__ p2)
{
    constexpr int N = 256;
    constexpr int KT = K/32, SA = 36, BS = N + 4;
    constexpr int WN = N/4, NT = WN/8, CT = N/32;
    extern __shared__ float smem[];
    float* sA = smem;              // [32][36]
    float* sB = smem + 32*SA;      // [32][260]
    const int tid = threadIdx.x, lane = tid & 31, warp = tid >> 5;
    const int wr = warp >> 2, wc = warp & 3;
    const int gid = lane >> 2, tig = lane & 3;
    const int rowBase = blockIdx.x*32;

    const int ar = tid >> 3, ac4 = tid & 7;   // A: 32 rows x 8 float4
    float4 rA;
    float4 rB[8];                             // B: 32x256/4/256 = 8 float4

    rA = *(const float4*)&A[(size_t)(rowBase + ar)*K + ac4*4];
    #pragma unroll
    for (int jj = 0; jj < 8; jj++) {
        int idx = tid + 256*jj;
        int r = idx >> 6, c4 = idx & 63;
        rB[jj] = *(const float4*)&Bw[(size_t)r*N + c4*4];
    }

    float acc[NT][4];
    #pragma unroll
    for (int t = 0; t < NT; t++) {
        int j0 = wc*WN + t*8 + tig*2;
        acc[t][0] = bias[j0];   acc[t][1] = bias[j0+1];
        acc[t][2] = bias[j0];   acc[t][3] = bias[j0+1];
    }

    for (int kt = 0; kt < KT; ++kt) {
        __syncthreads();
        {
            float* d = &sA[ar*SA + ac4*4];
            d[0] = tf32f(rA.x); d[1] = tf32f(rA.y); d[2] = tf32f(rA.z); d[3] = tf32f(rA.w);
            #pragma unroll
            for (int jj = 0; jj < 8; jj++) {
                int idx = tid + 256*jj;
                int r = idx >> 6, c4 = idx & 63;
                float* db = &sB[r*BS + c4*4];
                db[0] = tf32f(rB[jj].x); db[1] = tf32f(rB[jj].y);
                db[2] = tf32f(rB[jj].z); db[3] = tf32f(rB[jj].w);
            }
        }
        __syncthreads();
        if (kt + 1 < KT) {
            rA = *(const float4*)&A[(size_t)(rowBase + ar)*K + (kt+1)*32 + ac4*4];
            #pragma unroll
            for (int jj = 0; jj < 8; jj++) {
                int idx = tid + 256*jj;
                int r = idx >> 6, c4 = idx & 63;
                rB[jj] = *(const float4*)&Bw[(size_t)((kt+1)*32 + r)*N + c4*4];
            }
        }
        #pragma unroll
        for (int kk = 0; kk < 4; kk++) {
            uint32_t a0 = __float_as_uint(sA[(wr*16 + gid    )*SA + kk*8 + tig    ]);
            uint32_t a1 = __float_as_uint(sA[(wr*16 + gid + 8)*SA + kk*8 + tig    ]);
            uint32_t a2 = __float_as_uint(sA[(wr*16 + gid    )*SA + kk*8 + tig + 4]);
            uint32_t a3 = __float_as_uint(sA[(wr*16 + gid + 8)*SA + kk*8 + tig + 4]);
            #pragma unroll
            for (int t = 0; t < NT; t++) {
                int n0 = wc*WN + t*8;
                uint32_t b0 = __float_as_uint(sB[(kk*8 + tig    )*BS + n0 + gid]);
                uint32_t b1 = __float_as_uint(sB[(kk*8 + tig + 4)*BS + n0 + gid]);
                asm volatile(
                    "mma.sync.aligned.m16n8k8.row.col.f32.tf32.tf32.f32 "
                    "{%0,%1,%2,%3}, {%4,%5,%6,%7}, {%8,%9}, {%0,%1,%2,%3};"
                    : "+f"(acc[t][0]), "+f"(acc[t][1]), "+f"(acc[t][2]), "+f"(acc[t][3])
                    : "r"(a0), "r"(a1), "r"(a2), "r"(a3), "r"(b0), "r"(b1));
            }
        }
    }

    // stage through sB
    __syncthreads();
    #pragma unroll
    for (int t = 0; t < NT; t++) {
        int n0 = wc*WN + t*8 + tig*2;
        int r0 = wr*16 + gid;
        sB[ r0     *BS + n0    ] = acc[t][0];
        sB[ r0     *BS + n0 + 1] = acc[t][1];
        sB[(r0 + 8)*BS + n0    ] = acc[t][2];
        sB[(r0 + 8)*BS + n0 + 1] = acc[t][3];
    }
    __syncthreads();

    #pragma unroll
    for (int rr = 0; rr < 4; rr++) {
        int row = warp*4 + rr;
        int grow = rowBase + row;
        if (EPI == 1) {
            float v[CT]; float s = 0.f, s2 = 0.f;
            #pragma unroll
            for (int j = 0; j < CT; j++) {
                float x = sB[row*BS + lane + 32*j];
                x = 0.5f*x*(1.f + erff(x*0.70710678118654752f));
                v[j] = x; s += x; s2 += x*x;
            }
            #pragma unroll
            for (int o = 16; o; o >>= 1) {
                s  += __shfl_xor_sync(0xffffffffu, s,  o);
                s2 += __shfl_xor_sync(0xffffffffu, s2, o);
            }
            float mean = s*(1.f/256.f);
            float rstd = rsqrtf(s2*(1.f/256.f) - mean*mean + 1e-5f);
            #pragma unroll
            for (int j = 0; j < CT; j++) {
                int col = lane + 32*j;
                C[(size_t)grow*N + col] = (v[j]-mean)*rstd*p1[col] + p2[col];
            }
        } else {
            #pragma unroll
            for (int j = 0; j < CT; j++) {
                int col = lane + 32*j;
                C[(size_t)grow*N + col] = sB[row*BS + col] + p1[(size_t)grow*256 + col];
            }
        }
    }
}

// ---------------- fused per-token attention: 4 groups of 128 threads, 2 CTAs/SM ----------------
struct AttnGroup {
    float edge[32*ES];
    float logit[8*32];
    float attn[8*32];
    float kd[32*8];
    float qd[8];
    int   nbr[32];
    int   msk[32];
};
struct AttnSmem {
    float WeffT[8*132];   // transposed: [h][c]
    float lng[128];
    float lnb[128];
    float beff[8];
    float wfa[8];
    AttnGroup grp[4];
};

#define GBAR(id) asm volatile("bar.sync %0, 128;" :: "r"(id) : "memory")

__global__ __launch_bounds__(512, 2)
void attn_kernel(const float* __restrict__ edge_feats,
                 const float* __restrict__ geo_feats,
                 const int*   __restrict__ nbr_idx,
                 const int*   __restrict__ masks,
                 const float* __restrict__ ln_e_g,
                 const float* __restrict__ ln_e_b,
                 const float* __restrict__ W_fa,
                 const float* __restrict__ b_fa,
                 float* __restrict__ out_geo)
{
    extern __shared__ char smraw[];
    AttnSmem& sm = *reinterpret_cast<AttnSmem*>(smraw);
    const int tid = threadIdx.x;

    for (int i = tid; i < 8*128; i += 512) {
        int h = i >> 7, c = i & 127;
        sm.WeffT[h*132 + c] = g_weff[c*8 + h];
    }
    if (tid < 128) { sm.lng[tid] = ln_e_g[tid]; sm.lnb[tid] = ln_e_b[tid]; }
    if (tid >= 128 && tid < 136) { sm.beff[tid-128] = g_beff[tid-128]; sm.wfa[tid-128] = W_fa[tid-128]; }
    const float bfa = b_fa[0];
    __syncthreads();

    const int g     = tid >> 7;
    const int gtid  = tid & 127;
    const int glane = gtid & 31;
    const int gwarp = gtid >> 5;
    const int bid   = 1 + g;
    AttnGroup& G = sm.grp[g];

    for (int tok = 0; tok < 2; ++tok) {
        const int n = blockIdx.x*8 + g*2 + tok;

        // phase 1: loads
        {
            const float4* ep4 = (const float4*)(edge_feats + (size_t)n*4096);
            #pragma unroll
            for (int jj = 0; jj < 8; jj++) {
                int idx = gtid + 128*jj;
                int m = idx >> 5, c4 = idx & 31;
                *(float4*)&G.edge[m*ES + c4*4] = ep4[idx];
            }
            if (gtid < 32) { G.nbr[gtid] = nbr_idx[n*32 + gtid]; G.msk[gtid] = masks[n*32 + gtid]; }
            if (gtid >= 32 && gtid < 40) G.qd[gtid-32] = g_qkv[(size_t)n*QS + 256 + gtid-32];
        }
        GBAR(bid);

        // phase 2: kd gather + edge LN
        {
            #pragma unroll
            for (int jj = 0; jj < 2; jj++) {
                int item = gtid + 128*jj;
                int m = item >> 3, h = item & 7;
                G.kd[item] = g_qkv[(size_t)G.nbr[m]*QS + 264 + h];
            }
            #pragma unroll
            for (int i = 0; i < 8; i++) {
                int m = gwarp + 4*i;
                float v0 = G.edge[m*ES + glane];
                float v1 = G.edge[m*ES + glane + 32];
                float v2 = G.edge[m*ES + glane + 64];
                float v3 = G.edge[m*ES + glane + 96];
                float s  = v0+v1+v2+v3;
                float s2 = v0*v0+v1*v1+v2*v2+v3*v3;
                #pragma unroll
                for (int o = 16; o; o >>= 1) {
                    s  += __shfl_xor_sync(0xffffffffu, s,  o);
                    s2 += __shfl_xor_sync(0xffffffffu, s2, o);
                }
                float mean = s*(1.f/128.f);
                float rstd = rsqrtf(s2*(1.f/128.f) - mean*mean + 1e-5f);
                G.edge[m*ES + glane]      = (v0-mean)*rstd*sm.lng[glane]    + sm.lnb[glane];
                G.edge[m*ES + glane + 32] = (v1-mean)*rstd*sm.lng[glane+32] + sm.lnb[glane+32];
                G.edge[m*ES + glane + 64] = (v2-mean)*rstd*sm.lng[glane+64] + sm.lnb[glane+64];
                G.edge[m*ES + glane + 96] = (v3-mean)*rstd*sm.lng[glane+96] + sm.lnb[glane+96];
            }
        }
        GBAR(bid);

        // phase 3: logits (vectorized)
        {
            int m0 = gtid >> 3, h = gtid & 7;
            float a0 = G.qd[h] + G.kd[m0*8 + h]      + sm.beff[h];
            float a1 = G.qd[h] + G.kd[(m0+16)*8 + h] + sm.beff[h];
            const float4* e0 = (const float4*)&G.edge[m0*ES];
            const float4* e1 = (const float4*)&G.edge[(m0+16)*ES];
            const float4* wt = (const float4*)&sm.WeffT[h*132];
            #pragma unroll 8
            for (int c4 = 0; c4 < 32; c4++) {
                float4 w = wt[c4], x = e0[c4], y = e1[c4];
                a0 += x.x*w.x + x.y*w.y + x.z*w.z + x.w*w.w;
                a1 += y.x*w.x + y.y*w.y + y.z*w.z + y.w*w.w;
            }
            if (!G.msk[m0])    a0 = -1e9f;
            if (!G.msk[m0+16]) a1 = -1e9f;
            G.logit[h*32 + m0]      = a0;
            G.logit[h*32 + m0 + 16] = a1;
        }
        GBAR(bid);

        // phase 4: softmax (each warp: 2 heads)
        {
            #pragma unroll
            for (int i = 0; i < 2; i++) {
                int h = gwarp + 4*i;
                float l = G.logit[h*32 + glane];
                float mx = l;
                #pragma unroll
                for (int o = 16; o; o >>= 1) mx = fmaxf(mx, __shfl_xor_sync(0xffffffffu, mx, o));
                float e = __expf(l - mx);
                float ss = e;
                #pragma unroll
                for (int o = 16; o; o >>= 1) ss += __shfl_xor_sync(0xffffffffu, ss, o);
                G.attn[h*32 + glane] = e/ss;
            }
        }
        GBAR(bid);

        // phase 5: scalar ctx + ew (to gmem) + geo
        {
            float acc0 = 0.f, acc1 = 0.f;
            int c0 = gtid, c1 = gtid + 128;
            int h0 = c0 >> 5, h1 = c1 >> 5;
            #pragma unroll
            for (int m = 0; m < 32; m++) {
                const float* vrow = &g_qkv[(size_t)G.nbr[m]*QS];
                acc0 += G.attn[h0*32 + m]*vrow[c0];
                acc1 += G.attn[h1*32 + m]*vrow[c1];
            }
            g_hx[(size_t)n*HXS + c0] = acc0;
            g_hx[(size_t)n*HXS + c1] = acc1;

            float ewa[8];
            #pragma unroll
            for (int h = 0; h < 8; h++) ewa[h] = 0.f;
            #pragma unroll
            for (int m = 0; m < 32; m++) {
                float e = G.edge[m*ES + gtid];
                #pragma unroll
                for (int h = 0; h < 8; h++) ewa[h] += G.attn[h*32 + m]*e;
            }
            #pragma unroll
            for (int h = 0; h < 8; h++)
                g_hx[(size_t)n*HXS + 256 + h*128 + gtid] = ewa[h];
        }
        if (gwarp == 3) {
            int m = glane;
            float aw = 0.f;
            #pragma unroll
            for (int h = 0; h < 8; h++) aw += G.attn[h*32 + m]*sm.wfa[h];
            int nb = G.nbr[m];
            float p0 = aw*g_proj[nb*3 + 0];
            float p1 = aw*g_proj[nb*3 + 1];
            float p2 = aw*g_proj[nb*3 + 2];
            #pragma unroll
            for (int o = 16; o; o >>= 1) {
                p0 += __shfl_xor_sync(0xffffffffu, p0, o);
                p1 += __shfl_xor_sync(0xffffffffu, p1, o);
                p2 += __shfl_xor_sync(0xffffffffu, p2, o);
            }
            if (glane == 0) {
                int b = n >> 9;
                float ps[3] = {p0, p1, p2};
                float sd[3];
                #pragma unroll
                for (int j = 0; j < 3; j++)
                    sd[j] = 0.5f*(siluf(ps[j] + bfa) - siluf(-ps[j] + bfa));
                float gt = g_gate[n];
                #pragma unroll
                for (int i = 0; i < 3; i++) {
                    float gc = g_center[b*3 + i]
                             + sd[0]*g_V[b*9 + i*3 + 0]
                             + sd[1]*g_V[b*9 + i*3 + 1]
                             + sd[2]*g_V[b*9 + i*3 + 2];
                    out_geo[n*3 + i] = gc*gt + geo_feats[n*3 + i]*(1.f - gt);
                }
            }
        }
        GBAR(bid);
    }
}

// ---------------- launcher ----------------
extern "C" void kernel_launch(void* const* d_in, const int* in_sizes, int n_in,
                              void* d_out, int out_size)
{
    const float* token    = (const float*)d_in[0];
    const float* geo      = (const float*)d_in[1];
    const float* edge     = (const float*)d_in[2];
    const int*   nbr      = (const int*)d_in[3];
    const int*   mask     = (const int*)d_in[5];
    const float* ln_qkv_g = (const float*)d_in[6];
    const float* ln_qkv_b = (const float*)d_in[7];
    const float* W_qkv    = (const float*)d_in[8];
    const float* b_qkv    = (const float*)d_in[9];
    const float* ln_e_g   = (const float*)d_in[10];
    const float* ln_e_b   = (const float*)d_in[11];
    const float* W_qkv_e  = (const float*)d_in[12];
    const float* b_qkv_e  = (const float*)d_in[13];
    const float* w_attn   = (const float*)d_in[14];
    const float* w_edge   = (const float*)d_in[15];
    const float* W_gate   = (const float*)d_in[16];
    const float* b_gate   = (const float*)d_in[17];
    const float* W_fc1    = (const float*)d_in[18];
    const float* b_fc1    = (const float*)d_in[19];
    const float* ln_h_g   = (const float*)d_in[20];
    const float* ln_h_b   = (const float*)d_in[21];
    const float* W_fc2    = (const float*)d_in[22];
    const float* b_fc2    = (const float*)d_in[23];
    const float* W_fa     = (const float*)d_in[24];
    const float* b_fa     = (const float*)d_in[25];
    float* out = (float*)d_out;

    void* p;
    cudaGetSymbolAddress(&p, g_qkv);   float* p_qkv   = (float*)p;
    cudaGetSymbolAddress(&p, g_hx);    float* p_hx    = (float*)p;
    cudaGetSymbolAddress(&p, g_hmid);  float* p_hmid  = (float*)p;
    cudaGetSymbolAddress(&p, g_Wcomb); float* p_Wcomb = (float*)p;
    cudaGetSymbolAddress(&p, g_bcomb); float* p_bcomb = (float*)p;
    cudaGetSymbolAddress(&p, g_W1);    float* p_W1    = (float*)p;
    cudaGetSymbolAddress(&p, g_b1);    float* p_b1    = (float*)p;

    prep_kernel<<<64, 256>>>(W_qkv, b_qkv, w_attn, W_qkv_e, b_qkv_e, w_edge, W_fc1, b_fc1);
    geom_kernel<<<16, 256>>>(geo);

    // qkv: token -> LN -> @ Wcomb[256,288]
    {
        constexpr int SM = (32*292 + 32*292)*sizeof(float);
        cudaFuncSetAttribute((const void*)gemm_qkv,
                             cudaFuncAttributeMaxDynamicSharedMemorySize, SM);
        gemm_qkv<<<256, 256, SM>>>(token, p_Wcomb, p_bcomb, p_qkv,
                                   W_gate, b_gate, ln_qkv_g, ln_qkv_b);
    }

    cudaFuncSetAttribute(attn_kernel, cudaFuncAttributeMaxDynamicSharedMemorySize,
                         (int)sizeof(AttnSmem));
    attn_kernel<<<1024, 512, sizeof(AttnSmem)>>>(
        edge, geo, nbr, mask, ln_e_g, ln_e_b, W_fa, b_fa,
        out + (size_t)NTOK*256);

    // fc1 (folded): hx[8192,1280] @ W1[1280,256] -> gelu -> LN -> hmid
    {
        constexpr int SM = (32*36 + 32*260)*sizeof(float);
        cudaFuncSetAttribute((const void*)gemm_kt<HXS, 1>,
                             cudaFuncAttributeMaxDynamicSharedMemorySize, SM);
        gemm_kt<HXS, 1><<<256, 256, SM>>>(p_hx, p_W1, p_b1, p_hmid, ln_h_g, ln_h_b);
    }

    // fc2: hmid[8192,256] @ W_fc2[256,256] + token -> out
    {
        constexpr int SM = (32*36 + 32*260)*sizeof(float);
        cudaFuncSetAttribute((const void*)gemm_kt<256, 2>,
                             cudaFuncAttributeMaxDynamicSharedMemorySize, SM);
        gemm_kt<256, 2><<<256, 256, SM>>>(p_hmid, W_fc2, b_fc2, out, token, nullptr);
    }
}

// round 6
// speedup vs baseline: 1.0516x; 1.0516x over previous
#include <cuda_runtime.h>
#include <math.h>
#include <stdint.h>

#define NTOK 8192
#define QS 288            // qkv row stride: 256 v | 8 qdot | 8 kdot | pad
#define ES 132            // edge smem row stride (floats)
#define HXS 1280          // hx row stride: 256 scalar ctx | 1024 ew

// ---------------- device scratch ----------------
__device__ float g_qkv[NTOK*QS];
__device__ float g_hx[NTOK*HXS];
__device__ float g_hmid[NTOK*256];
__device__ float g_gate[NTOK];
__device__ float g_proj[NTOK*3];
__device__ float g_center[16*3];
__device__ float g_V[16*9];
__device__ float g_Wcomb[256*QS];
__device__ float g_bcomb[QS];
__device__ float g_weff[128*8];
__device__ float g_beff[8];
__device__ float g_W1[HXS*256];     // folded fc1 weight: [1280, 256]
__device__ float g_b1[256];         // folded fc1 bias

__device__ __forceinline__ float siluf(float x){ return x/(1.f+__expf(-x)); }
__device__ __forceinline__ uint32_t f2tf32(float x){
    uint32_t u; asm("cvt.rna.tf32.f32 %0, %1;" : "=r"(u) : "f"(x)); return u;
}
__device__ __forceinline__ float tf32f(float x){ return __uint_as_float(f2tf32(x)); }

// ---------------- prep: fold effective weights ----------------
__global__ void prep_kernel(const float* __restrict__ W_qkv, const float* __restrict__ b_qkv,
                            const float* __restrict__ w_attn,
                            const float* __restrict__ W_qkv_e, const float* __restrict__ b_qkv_e,
                            const float* __restrict__ w_edge,
                            const float* __restrict__ W_fc1, const float* __restrict__ b_fc1)
{
    int gid = blockIdx.x*blockDim.x + threadIdx.x;
    int gstride = gridDim.x*blockDim.x;
    for (int idx = gid; idx < 256*QS; idx += gstride) {
        int c = idx / QS, j = idx - c*QS;
        float w = 0.f;
        if (j < 256) {
            w = W_qkv[c*768 + 512 + j];
        } else if (j < 264) {
            int h = j - 256; float s = 0.f;
            #pragma unroll
            for (int d = 0; d < 32; d++) s += W_qkv[c*768 + h*32 + d]*w_attn[d];
            w = s;
        } else if (j < 272) {
            int h = j - 264; float s = 0.f;
            #pragma unroll
            for (int d = 0; d < 32; d++) s += W_qkv[c*768 + 256 + h*32 + d]*w_attn[d];
            w = s;
        }
        g_Wcomb[idx] = w;
    }
    // W1 [1280, 256]: rows 0..255 = W_fc1[0:256]; rows 256.. = fold(Wve, W1b)
    for (int idx = gid; idx < HXS*256; idx += gstride) {
        int j = idx >> 8, o = idx & 255;
        float w;
        if (j < 256) {
            w = W_fc1[j*256 + o];
        } else {
            int hc = j - 256, h = hc >> 7, c = hc & 127;
            float s = 0.f;
            #pragma unroll
            for (int jp = 0; jp < 16; jp++)
                s += W_qkv_e[c*256 + 128 + h*16 + jp]*W_fc1[(256 + h*16 + jp)*256 + o];
            w = s;
        }
        g_W1[idx] = w;
    }
    if (blockIdx.x == 0) {
        for (int j = threadIdx.x; j < QS; j += blockDim.x) {
            float bv = 0.f;
            if (j < 256) bv = b_qkv[512 + j];
            else if (j < 264) { int h = j-256; for (int d=0; d<32; d++) bv += b_qkv[h*32+d]*w_attn[d]; }
            else if (j < 272) { int h = j-264; for (int d=0; d<32; d++) bv += b_qkv[256 + h*32+d]*w_attn[d]; }
            g_bcomb[j] = bv;
        }
    }
    if (blockIdx.x == 1) {
        for (int idx = threadIdx.x; idx < 128*8; idx += blockDim.x) {
            int c = idx >> 3, h = idx & 7; float s = 0.f;
            #pragma unroll
            for (int e = 0; e < 16; e++) s += W_qkv_e[c*256 + h*16 + e]*w_edge[e];
            g_weff[idx] = s;
        }
        if (threadIdx.x < 8) {
            float s = 0.f;
            for (int e = 0; e < 16; e++) s += b_qkv_e[threadIdx.x*16 + e]*w_edge[e];
            g_beff[threadIdx.x] = s;
        }
    }
    if (blockIdx.x == 2 && threadIdx.x < 256) {
        int o = threadIdx.x;
        float s = b_fc1[o];
        for (int j = 0; j < 128; j++)
            s += b_qkv_e[128 + j]*W_fc1[(256 + j)*256 + o];
        g_b1[o] = s;
    }
}

// ---------------- per-graph geometry ----------------
__device__ void jacobi3(double a00,double a01,double a02,double a11,double a12,double a22,
                        double V[3][3])
{
    double A[3][3] = {{a00,a01,a02},{a01,a11,a12},{a02,a12,a22}};
    V[0][0]=1; V[0][1]=0; V[0][2]=0;
    V[1][0]=0; V[1][1]=1; V[1][2]=0;
    V[2][0]=0; V[2][1]=0; V[2][2]=1;
    for (int it = 0; it < 60; ++it) {
        int p = 0, q = 1; double mx = fabs(A[0][1]);
        if (fabs(A[0][2]) > mx) { mx = fabs(A[0][2]); p = 0; q = 2; }
        if (fabs(A[1][2]) > mx) { mx = fabs(A[1][2]); p = 1; q = 2; }
        if (mx <= 1e-13*(fabs(A[0][0])+fabs(A[1][1])+fabs(A[2][2]))) break;
        double apq = A[p][q];
        double theta = (A[q][q]-A[p][p])/(2.0*apq);
        double t = 1.0/(fabs(theta)+sqrt(theta*theta+1.0));
        if (theta < 0) t = -t;
        double c = 1.0/sqrt(t*t+1.0), s = t*c;
        for (int k = 0; k < 3; k++) { double akp=A[k][p], akq=A[k][q]; A[k][p]=c*akp-s*akq; A[k][q]=s*akp+c*akq; }
        for (int k = 0; k < 3; k++) { double apk=A[p][k], aqk=A[q][k]; A[p][k]=c*apk-s*aqk; A[q][k]=s*apk+c*aqk; }
        for (int k = 0; k < 3; k++) { double vkp=V[k][p], vkq=V[k][q]; V[k][p]=c*vkp-s*vkq; V[k][q]=s*vkp+c*vkq; }
    }
}

__global__ void geom_kernel(const float* __restrict__ geo)
{
    __shared__ double sred[8][9];
    __shared__ double sCd[3];
    __shared__ float sV[9], sC[3];
    int b = blockIdx.x, tid = threadIdx.x, lane = tid & 31, warp = tid >> 5;
    const float* G = geo + (size_t)b*512*3;

    {
        double s[3] = {0,0,0};
        for (int p = tid; p < 512; p += 256) { s[0] += G[p*3]; s[1] += G[p*3+1]; s[2] += G[p*3+2]; }
        #pragma unroll
        for (int k = 0; k < 3; k++)
            #pragma unroll
            for (int o = 16; o; o >>= 1) s[k] += __shfl_xor_sync(0xffffffffu, s[k], o);
        if (lane == 0) { sred[warp][0]=s[0]; sred[warp][1]=s[1]; sred[warp][2]=s[2]; }
    }
    __syncthreads();
    if (tid == 0) {
        for (int k = 0; k < 3; k++) {
            double t = 0; for (int w = 0; w < 8; w++) t += sred[w][k];
            sCd[k] = t/512.0;
        }
    }
    __syncthreads();
    double c0 = sCd[0], c1 = sCd[1], c2 = sCd[2];

    {
        double m[6] = {0,0,0,0,0,0};
        for (int p = tid; p < 512; p += 256) {
            double dx = G[p*3]-c0, dy = G[p*3+1]-c1, dz = G[p*3+2]-c2;
            m[0] += dx*dx; m[1] += dx*dy; m[2] += dx*dz;
            m[3] += dy*dy; m[4] += dy*dz; m[5] += dz*dz;
        }
        #pragma unroll
        for (int k = 0; k < 6; k++)
            #pragma unroll
            for (int o = 16; o; o >>= 1) m[k] += __shfl_xor_sync(0xffffffffu, m[k], o);
        if (lane == 0) for (int k = 0; k < 6; k++) sred[warp][k] = m[k];
    }
    __syncthreads();
    if (tid == 0) {
        double m[6];
        for (int k = 0; k < 6; k++) { double t=0; for (int w=0; w<8; w++) t += sred[w][k]; m[k]=t; }
        double V[3][3];
        jacobi3(m[0],m[1],m[2],m[3],m[4],m[5], V);
        for (int i = 0; i < 3; i++)
            for (int j = 0; j < 3; j++) { sV[i*3+j] = (float)V[i][j]; g_V[b*9+i*3+j] = (float)V[i][j]; }
        sC[0]=(float)c0; sC[1]=(float)c1; sC[2]=(float)c2;
        g_center[b*3+0]=(float)c0; g_center[b*3+1]=(float)c1; g_center[b*3+2]=(float)c2;
    }
    __syncthreads();

    for (int p = tid; p < 512; p += 256) {
        int t = b*512 + p;
        float dx = G[p*3]-sC[0], dy = G[p*3+1]-sC[1], dz = G[p*3+2]-sC[2];
        for (int d = 0; d < 3; d++)
            g_proj[t*3+d] = dx*sV[0*3+d] + dy*sV[1*3+d] + dz*sV[2*3+d];
    }
}

// ---------------- qkv GEMM: full-K A resident + LN + gate, B reg-prefetch ----------------
__global__ __launch_bounds__(256)
void gemm_qkv(const float* __restrict__ A, const float* __restrict__ Bw,
              const float* __restrict__ bias, float* __restrict__ C,
              const float* __restrict__ Wg, const float* __restrict__ bg,
              const float* __restrict__ lng, const float* __restrict__ lnb)
{
    constexpr int K = 256, N = QS;
    constexpr int SA = 292, BS = 292;
    constexpr int WN = N/4, NT = WN/8, CT = N/32, KT = K/32;
    extern __shared__ float smem[];
    float* sA = smem;
    float* sB = smem + 32*SA;
    const int tid = threadIdx.x, lane = tid & 31, warp = tid >> 5;
    const int wr = warp >> 2, wc = warp & 3;
    const int gid = lane >> 2, tig = lane & 3;
    const int rowBase = blockIdx.x*32;

    for (int i = tid; i < 32*64; i += 256) {
        int r = i >> 6, c4 = i & 63;
        *(float4*)&sA[r*SA + c4*4] = *(const float4*)&A[(size_t)(rowBase + r)*K + c4*4];
    }
    __syncthreads();
    #pragma unroll
    for (int rr = 0; rr < 4; rr++) {
        int row = warp*4 + rr;
        float v[8]; float s = 0.f, s2 = 0.f, gd = 0.f;
        #pragma unroll
        for (int j = 0; j < 8; j++) {
            int c = lane + 32*j;
            float t = sA[row*SA + c];
            v[j] = t; s += t; s2 += t*t; gd += t*Wg[c];
        }
        #pragma unroll
        for (int o = 16; o; o >>= 1) {
            s  += __shfl_xor_sync(0xffffffffu, s,  o);
            s2 += __shfl_xor_sync(0xffffffffu, s2, o);
            gd += __shfl_xor_sync(0xffffffffu, gd, o);
        }
        float mean = s*(1.f/256.f);
        float rstd = rsqrtf(s2*(1.f/256.f) - mean*mean + 1e-5f);
        #pragma unroll
        for (int j = 0; j < 8; j++) {
            int c = lane + 32*j;
            sA[row*SA + c] = tf32f((v[j]-mean)*rstd*lng[c] + lnb[c]);
        }
        if (lane == 0) g_gate[rowBase + row] = 1.f/(1.f + __expf(-(gd + bg[0])));
    }

    float acc[NT][4];
    #pragma unroll
    for (int t = 0; t < NT; t++) {
        int j0 = wc*WN + t*8 + tig*2;
        acc[t][0] = bias[j0];   acc[t][1] = bias[j0+1];
        acc[t][2] = bias[j0];   acc[t][3] = bias[j0+1];
    }

    float4 rB[9];
    #pragma unroll
    for (int jj = 0; jj < 9; jj++) {
        int idx = tid + 256*jj;
        int r = idx/72, c4 = idx - r*72;
        rB[jj] = *(const float4*)&Bw[(size_t)r*N + c4*4];
    }
    for (int kt = 0; kt < KT; ++kt) {
        __syncthreads();
        #pragma unroll
        for (int jj = 0; jj < 9; jj++) {
            int idx = tid + 256*jj;
            int r = idx/72, c4 = idx - r*72;
            float* d = &sB[r*BS + c4*4];
            d[0] = tf32f(rB[jj].x); d[1] = tf32f(rB[jj].y);
            d[2] = tf32f(rB[jj].z); d[3] = tf32f(rB[jj].w);
        }
        __syncthreads();
        if (kt + 1 < KT) {
            #pragma unroll
            for (int jj = 0; jj < 9; jj++) {
                int idx = tid + 256*jj;
                int r = idx/72, c4 = idx - r*72;
                rB[jj] = *(const float4*)&Bw[(size_t)((kt+1)*32 + r)*N + c4*4];
            }
        }
        #pragma unroll
        for (int kk = 0; kk < 4; kk++) {
            int kc = kt*32 + kk*8;
            uint32_t a0 = __float_as_uint(sA[(wr*16 + gid    )*SA + kc + tig    ]);
            uint32_t a1 = __float_as_uint(sA[(wr*16 + gid + 8)*SA + kc + tig    ]);
            uint32_t a2 = __float_as_uint(sA[(wr*16 + gid    )*SA + kc + tig + 4]);
            uint32_t a3 = __float_as_uint(sA[(wr*16 + gid + 8)*SA + kc + tig + 4]);
            #pragma unroll
            for (int t = 0; t < NT; t++) {
                int n0 = wc*WN + t*8;
                uint32_t b0 = __float_as_uint(sB[(kk*8 + tig    )*BS + n0 + gid]);
                uint32_t b1 = __float_as_uint(sB[(kk*8 + tig + 4)*BS + n0 + gid]);
                asm volatile(
                    "mma.sync.aligned.m16n8k8.row.col.f32.tf32.tf32.f32 "
                    "{%0,%1,%2,%3}, {%4,%5,%6,%7}, {%8,%9}, {%0,%1,%2,%3};"
                    : "+f"(acc[t][0]), "+f"(acc[t][1]), "+f"(acc[t][2]), "+f"(acc[t][3])
                    : "r"(a0), "r"(a1), "r"(a2), "r"(a3), "r"(b0), "r"(b1));
            }
        }
    }

    __syncthreads();
    #pragma unroll
    for (int t = 0; t < NT; t++) {
        int n0 = wc*WN + t*8 + tig*2;
        int r0 = wr*16 + gid;
        sA[ r0     *SA + n0    ] = acc[t][0];
        sA[ r0     *SA + n0 + 1] = acc[t][1];
        sA[(r0 + 8)*SA + n0    ] = acc[t][2];
        sA[(r0 + 8)*SA + n0 + 1] = acc[t][3];
    }
    __syncthreads();
    #pragma unroll
    for (int rr = 0; rr < 4; rr++) {
        int row = warp*4 + rr;
        int grow = rowBase + row;
        #pragma unroll
        for (int j = 0; j < CT; j++) {
            int col = lane + 32*j;
            C[(size_t)grow*N + col] = sA[row*SA + col];
        }
    }
}

// ---------------- BM=64 K-tiled tf32 GEMM, reg-prefetch, 8 warps = 4x2 ----------------
// EPI: 1 = gelu+LN, 2 = +residual. N=256.
template<int K, int EPI>
__global__ __launch_bounds__(256)
void gemm_kt64(const float* __restrict__ A, const float* __restrict__ Bw,
               const float* __restrict__ bias, float* __restrict__ C,
               const float* __restrict__ p1, const float* __restrict__ p2)
{
    constexpr int N = 256;
    constexpr int KT = K/32, SA = 36, BS = N + 4;
    constexpr int NT = 16, CT = N/32;   // warp: 16 rows x 128 cols
    extern __shared__ float smem[];
    float* sA = smem;                   // [64][36]
    float* sB = smem + 64*SA;           // [32][260]
    float* sC = smem;                   // staging [64][260] (reuses everything)
    const int tid = threadIdx.x, lane = tid & 31, warp = tid >> 5;
    const int wr = warp >> 1, wc = warp & 1;
    const int gid = lane >> 2, tig = lane & 3;
    const int rowBase = blockIdx.x*64;

    float4 rA[2], rB[8];
    #pragma unroll
    for (int jj = 0; jj < 2; jj++) {
        int idx = tid + 256*jj;
        int r = idx >> 3, c4 = idx & 7;
        rA[jj] = *(const float4*)&A[(size_t)(rowBase + r)*K + c4*4];
    }
    #pragma unroll
    for (int jj = 0; jj < 8; jj++) {
        int idx = tid + 256*jj;
        int r = idx >> 6, c4 = idx & 63;
        rB[jj] = *(const float4*)&Bw[(size_t)r*N + c4*4];
    }

    float acc[NT][4];
    #pragma unroll
    for (int t = 0; t < NT; t++) {
        int j0 = wc*128 + t*8 + tig*2;
        acc[t][0] = bias[j0];   acc[t][1] = bias[j0+1];
        acc[t][2] = bias[j0];   acc[t][3] = bias[j0+1];
    }

    for (int kt = 0; kt < KT; ++kt) {
        __syncthreads();
        #pragma unroll
        for (int jj = 0; jj < 2; jj++) {
            int idx = tid + 256*jj;
            int r = idx >> 3, c4 = idx & 7;
            float* d = &sA[r*SA + c4*4];
            d[0] = tf32f(rA[jj].x); d[1] = tf32f(rA[jj].y);
            d[2] = tf32f(rA[jj].z); d[3] = tf32f(rA[jj].w);
        }
        #pragma unroll
        for (int jj = 0; jj < 8; jj++) {
            int idx = tid + 256*jj;
            int r = idx >> 6, c4 = idx & 63;
            float* d = &sB[r*BS + c4*4];
            d[0] = tf32f(rB[jj].x); d[1] = tf32f(rB[jj].y);
            d[2] = tf32f(rB[jj].z); d[3] = tf32f(rB[jj].w);
        }
        __syncthreads();
        if (kt + 1 < KT) {
            #pragma unroll
            for (int jj = 0; jj < 2; jj++) {
                int idx = tid + 256*jj;
                int r = idx >> 3, c4 = idx & 7;
                rA[jj] = *(const float4*)&A[(size_t)(rowBase + r)*K + (kt+1)*32 + c4*4];
            }
            #pragma unroll
            for (int jj = 0; jj < 8; jj++) {
                int idx = tid + 256*jj;
                int r = idx >> 6, c4 = idx & 63;
                rB[jj] = *(const float4*)&Bw[(size_t)((kt+1)*32 + r)*N + c4*4];
            }
        }
        #pragma unroll
        for (int kk = 0; kk < 4; kk++) {
            uint32_t a0 = __float_as_uint(sA[(wr*16 + gid    )*SA + kk*8 + tig    ]);
            uint32_t a1 = __float_as_uint(sA[(wr*16 + gid + 8)*SA + kk*8 + tig    ]);
            uint32_t a2 = __float_as_uint(sA[(wr*16 + gid    )*SA + kk*8 + tig + 4]);
            uint32_t a3 = __float_as_uint(sA[(wr*16 + gid + 8)*SA + kk*8 + tig + 4]);
            #pragma unroll
            for (int t = 0; t < NT; t++) {
                int n0 = wc*128 + t*8;
                uint32_t b0 = __float_as_uint(sB[(kk*8 + tig    )*BS + n0 + gid]);
                uint32_t b1 = __float_as_uint(sB[(kk*8 + tig + 4)*BS + n0 + gid]);
                asm volatile(
                    "mma.sync.aligned.m16n8k8.row.col.f32.tf32.tf32.f32 "
                    "{%0,%1,%2,%3}, {%4,%5,%6,%7}, {%8,%9}, {%0,%1,%2,%3};"
                    : "+f"(acc[t][0]), "+f"(acc[t][1]), "+f"(acc[t][2]), "+f"(acc[t][3])
                    : "r"(a0), "r"(a1), "r"(a2), "r"(a3), "r"(b0), "r"(b1));
            }
        }
    }

    // stage C [64][260] over all smem
    __syncthreads();
    #pragma unroll
    for (int t = 0; t < NT; t++) {
        int n0 = wc*128 + t*8 + tig*2;
        int r0 = wr*16 + gid;
        sC[ r0     *BS + n0    ] = acc[t][0];
        sC[ r0     *BS + n0 + 1] = acc[t][1];
        sC[(r0 + 8)*BS + n0    ] = acc[t][2];
        sC[(r0 + 8)*BS + n0 + 1] = acc[t][3];
    }
    __syncthreads();

    // warp handles 8 rows
    #pragma unroll
    for (int rr = 0; rr < 8; rr++) {
        int row = warp*8 + rr;
        int grow = rowBase + row;
        if (EPI == 1) {
            float v[CT]; float s = 0.f, s2 = 0.f;
            #pragma unroll
            for (int j = 0; j < CT; j++) {
                float x = sC[row*BS + lane + 32*j];
                x = 0.5f*x*(1.f + erff(x*0.70710678118654752f));
                v[j] = x; s += x; s2 += x*x;
            }
            #pragma unroll
            for (int o = 16; o; o >>= 1) {
                s  += __shfl_xor_sync(0xffffffffu, s,  o);
                s2 += __shfl_xor_sync(0xffffffffu, s2, o);
            }
            float mean = s*(1.f/256.f);
            float rstd = rsqrtf(s2*(1.f/256.f) - mean*mean + 1e-5f);
            #pragma unroll
            for (int j = 0; j < CT; j++) {
                int col = lane + 32*j;
                C[(size_t)grow*256 + col] = (v[j]-mean)*rstd*p1[col] + p2[col];
            }
        } else {
            #pragma unroll
            for (int j = 0; j < CT; j++) {
                int col = lane + 32*j;
                C[(size_t)grow*256 + col] = sC[row*BS + col] + p1[(size_t)grow*256 + col];
            }
        }
    }
}

// ---------------- fused per-token attention: 4 groups of 128 threads, 2 CTAs/SM ----------------
struct AttnGroup {
    float edge[32*ES];
    float logit[8*32];
    float attn[8*32];
    float kd[32*8];
    float qd[8];
    int   nbr[32];
    int   msk[32];
};
struct AttnSmem {
    float WeffT[8*132];
    float lng[128];
    float lnb[128];
    float beff[8];
    float wfa[8];
    AttnGroup grp[4];
};

#define GBAR(id) asm volatile("bar.sync %0, 128;" :: "r"(id) : "memory")

__global__ __launch_bounds__(512, 2)
void attn_kernel(const float* __restrict__ edge_feats,
                 const float* __restrict__ geo_feats,
                 const int*   __restrict__ nbr_idx,
                 const int*   __restrict__ masks,
                 const float* __restrict__ ln_e_g,
                 const float* __restrict__ ln_e_b,
                 const float* __restrict__ W_fa,
                 const float* __restrict__ b_fa,
                 float* __restrict__ out_geo)
{
    extern __shared__ char smraw[];
    AttnSmem& sm = *reinterpret_cast<AttnSmem*>(smraw);
    const int tid = threadIdx.x;

    for (int i = tid; i < 8*128; i += 512) {
        int h = i >> 7, c = i & 127;
        sm.WeffT[h*132 + c] = g_weff[c*8 + h];
    }
    if (tid < 128) { sm.lng[tid] = ln_e_g[tid]; sm.lnb[tid] = ln_e_b[tid]; }
    if (tid >= 128 && tid < 136) { sm.beff[tid-128] = g_beff[tid-128]; sm.wfa[tid-128] = W_fa[tid-128]; }
    const float bfa = b_fa[0];
    __syncthreads();

    const int g     = tid >> 7;
    const int gtid  = tid & 127;
    const int glane = gtid & 31;
    const int gwarp = gtid >> 5;
    const int bid   = 1 + g;
    AttnGroup& G = sm.grp[g];

    for (int tok = 0; tok < 2; ++tok) {
        const int n = blockIdx.x*8 + g*2 + tok;

        {
            const float4* ep4 = (const float4*)(edge_feats + (size_t)n*4096);
            #pragma unroll
            for (int jj = 0; jj < 8; jj++) {
                int idx = gtid + 128*jj;
                int m = idx >> 5, c4 = idx & 31;
                *(float4*)&G.edge[m*ES + c4*4] = ep4[idx];
            }
            if (gtid < 32) { G.nbr[gtid] = nbr_idx[n*32 + gtid]; G.msk[gtid] = masks[n*32 + gtid]; }
            if (gtid >= 32 && gtid < 40) G.qd[gtid-32] = g_qkv[(size_t)n*QS + 256 + gtid-32];
        }
        GBAR(bid);

        {
            #pragma unroll
            for (int jj = 0; jj < 2; jj++) {
                int item = gtid + 128*jj;
                int m = item >> 3, h = item & 7;
                G.kd[item] = g_qkv[(size_t)G.nbr[m]*QS + 264 + h];
            }
            #pragma unroll
            for (int i = 0; i < 8; i++) {
                int m = gwarp + 4*i;
                float v0 = G.edge[m*ES + glane];
                float v1 = G.edge[m*ES + glane + 32];
                float v2 = G.edge[m*ES + glane + 64];
                float v3 = G.edge[m*ES + glane + 96];
                float s  = v0+v1+v2+v3;
                float s2 = v0*v0+v1*v1+v2*v2+v3*v3;
                #pragma unroll
                for (int o = 16; o; o >>= 1) {
                    s  += __shfl_xor_sync(0xffffffffu, s,  o);
                    s2 += __shfl_xor_sync(0xffffffffu, s2, o);
                }
                float mean = s*(1.f/128.f);
                float rstd = rsqrtf(s2*(1.f/128.f) - mean*mean + 1e-5f);
                G.edge[m*ES + glane]      = (v0-mean)*rstd*sm.lng[glane]    + sm.lnb[glane];
                G.edge[m*ES + glane + 32] = (v1-mean)*rstd*sm.lng[glane+32] + sm.lnb[glane+32];
                G.edge[m*ES + glane + 64] = (v2-mean)*rstd*sm.lng[glane+64] + sm.lnb[glane+64];
                G.edge[m*ES + glane + 96] = (v3-mean)*rstd*sm.lng[glane+96] + sm.lnb[glane+96];
            }
        }
        GBAR(bid);

        {
            int m0 = gtid >> 3, h = gtid & 7;
            float a0 = G.qd[h] + G.kd[m0*8 + h]      + sm.beff[h];
            float a1 = G.qd[h] + G.kd[(m0+16)*8 + h] + sm.beff[h];
            const float4* e0 = (const float4*)&G.edge[m0*ES];
            const float4* e1 = (const float4*)&G.edge[(m0+16)*ES];
            const float4* wt = (const float4*)&sm.WeffT[h*132];
            #pragma unroll 8
            for (int c4 = 0; c4 < 32; c4++) {
                float4 w = wt[c4], x = e0[c4], y = e1[c4];
                a0 += x.x*w.x + x.y*w.y + x.z*w.z + x.w*w.w;
                a1 += y.x*w.x + y.y*w.y + y.z*w.z + y.w*w.w;
            }
            if (!G.msk[m0])    a0 = -1e9f;
            if (!G.msk[m0+16]) a1 = -1e9f;
            G.logit[h*32 + m0]      = a0;
            G.logit[h*32 + m0 + 16] = a1;
        }
        GBAR(bid);

        {
            #pragma unroll
            for (int i = 0; i < 2; i++) {
                int h = gwarp + 4*i;
                float l = G.logit[h*32 + glane];
                float mx = l;
                #pragma unroll
                for (int o = 16; o; o >>= 1) mx = fmaxf(mx, __shfl_xor_sync(0xffffffffu, mx, o));
                float e = __expf(l - mx);
                float ss = e;
                #pragma unroll
                for (int o = 16; o; o >>= 1) ss += __shfl_xor_sync(0xffffffffu, ss, o);
                G.attn[h*32 + glane] = e/ss;
            }
        }
        GBAR(bid);

        {
            float acc0 = 0.f, acc1 = 0.f;
            int c0 = gtid, c1 = gtid + 128;
            int h0 = c0 >> 5, h1 = c1 >> 5;
            #pragma unroll
            for (int m = 0; m < 32; m++) {
                const float* vrow = &g_qkv[(size_t)G.nbr[m]*QS];
                acc0 += G.attn[h0*32 + m]*vrow[c0];
                acc1 += G.attn[h1*32 + m]*vrow[c1];
            }
            g_hx[(size_t)n*HXS + c0] = acc0;
            g_hx[(size_t)n*HXS + c1] = acc1;

            float ewa[8];
            #pragma unroll
            for (int h = 0; h < 8; h++) ewa[h] = 0.f;
            #pragma unroll
            for (int m = 0; m < 32; m++) {
                float e = G.edge[m*ES + gtid];
                #pragma unroll
                for (int h = 0; h < 8; h++) ewa[h] += G.attn[h*32 + m]*e;
            }
            #pragma unroll
            for (int h = 0; h < 8; h++)
                g_hx[(size_t)n*HXS + 256 + h*128 + gtid] = ewa[h];
        }
        if (gwarp == 3) {
            int m = glane;
            float aw = 0.f;
            #pragma unroll
            for (int h = 0; h < 8; h++) aw += G.attn[h*32 + m]*sm.wfa[h];
            int nb = G.nbr[m];
            float p0 = aw*g_proj[nb*3 + 0];
            float p1 = aw*g_proj[nb*3 + 1];
            float p2 = aw*g_proj[nb*3 + 2];
            #pragma unroll
            for (int o = 16; o; o >>= 1) {
                p0 += __shfl_xor_sync(0xffffffffu, p0, o);
                p1 += __shfl_xor_sync(0xffffffffu, p1, o);
                p2 += __shfl_xor_sync(0xffffffffu, p2, o);
            }
            if (glane == 0) {
                int b = n >> 9;
                float ps[3] = {p0, p1, p2};
                float sd[3];
                #pragma unroll
                for (int j = 0; j < 3; j++)
                    sd[j] = 0.5f*(siluf(ps[j] + bfa) - siluf(-ps[j] + bfa));
                float gt = g_gate[n];
                #pragma unroll
                for (int i = 0; i < 3; i++) {
                    float gc = g_center[b*3 + i]
                             + sd[0]*g_V[b*9 + i*3 + 0]
                             + sd[1]*g_V[b*9 + i*3 + 1]
                             + sd[2]*g_V[b*9 + i*3 + 2];
                    out_geo[n*3 + i] = gc*gt + geo_feats[n*3 + i]*(1.f - gt);
                }
            }
        }
        GBAR(bid);
    }
}

// ---------------- launcher ----------------
extern "C" void kernel_launch(void* const* d_in, const int* in_sizes, int n_in,
                              void* d_out, int out_size)
{
    const float* token    = (const float*)d_in[0];
    const float* geo      = (const float*)d_in[1];
    const float* edge     = (const float*)d_in[2];
    const int*   nbr      = (const int*)d_in[3];
    const int*   mask     = (const int*)d_in[5];
    const float* ln_qkv_g = (const float*)d_in[6];
    const float* ln_qkv_b = (const float*)d_in[7];
    const float* W_qkv    = (const float*)d_in[8];
    const float* b_qkv    = (const float*)d_in[9];
    const float* ln_e_g   = (const float*)d_in[10];
    const float* ln_e_b   = (const float*)d_in[11];
    const float* W_qkv_e  = (const float*)d_in[12];
    const float* b_qkv_e  = (const float*)d_in[13];
    const float* w_attn   = (const float*)d_in[14];
    const float* w_edge   = (const float*)d_in[15];
    const float* W_gate   = (const float*)d_in[16];
    const float* b_gate   = (const float*)d_in[17];
    const float* W_fc1    = (const float*)d_in[18];
    const float* b_fc1    = (const float*)d_in[19];
    const float* ln_h_g   = (const float*)d_in[20];
    const float* ln_h_b   = (const float*)d_in[21];
    const float* W_fc2    = (const float*)d_in[22];
    const float* b_fc2    = (const float*)d_in[23];
    const float* W_fa     = (const float*)d_in[24];
    const float* b_fa     = (const float*)d_in[25];
    float* out = (float*)d_out;

    void* p;
    cudaGetSymbolAddress(&p, g_qkv);   float* p_qkv   = (float*)p;
    cudaGetSymbolAddress(&p, g_hx);    float* p_hx    = (float*)p;
    cudaGetSymbolAddress(&p, g_hmid);  float* p_hmid  = (float*)p;
    cudaGetSymbolAddress(&p, g_Wcomb); float* p_Wcomb = (float*)p;
    cudaGetSymbolAddress(&p, g_bcomb); float* p_bcomb = (float*)p;
    cudaGetSymbolAddress(&p, g_W1);    float* p_W1    = (float*)p;
    cudaGetSymbolAddress(&p, g_b1);    float* p_b1    = (float*)p;

    prep_kernel<<<64, 256>>>(W_qkv, b_qkv, w_attn, W_qkv_e, b_qkv_e, w_edge, W_fc1, b_fc1);
    geom_kernel<<<16, 256>>>(geo);

    {
        constexpr int SM = (32*292 + 32*292)*sizeof(float);
        cudaFuncSetAttribute((const void*)gemm_qkv,
                             cudaFuncAttributeMaxDynamicSharedMemorySize, SM);
        gemm_qkv<<<256, 256, SM>>>(token, p_Wcomb, p_bcomb, p_qkv,
                                   W_gate, b_gate, ln_qkv_g, ln_qkv_b);
    }

    cudaFuncSetAttribute(attn_kernel, cudaFuncAttributeMaxDynamicSharedMemorySize,
                         (int)sizeof(AttnSmem));
    attn_kernel<<<1024, 512, sizeof(AttnSmem)>>>(
        edge, geo, nbr, mask, ln_e_g, ln_e_b, W_fa, b_fa,
        out + (size_t)NTOK*256);

    // fc1 (folded): hx[8192,1280] @ W1[1280,256] -> gelu -> LN -> hmid
    {
        constexpr int SM = 64*260*sizeof(float);   // >= (64*36 + 32*260)*4
        cudaFuncSetAttribute((const void*)gemm_kt64<HXS, 1>,
                             cudaFuncAttributeMaxDynamicSharedMemorySize, SM);
        gemm_kt64<HXS, 1><<<128, 256, SM>>>(p_hx, p_W1, p_b1, p_hmid, ln_h_g, ln_h_b);
    }

    // fc2: hmid[8192,256] @ W_fc2[256,256] + token -> out
    {
        constexpr int SM = 64*260*sizeof(float);
        cudaFuncSetAttribute((const void*)gemm_kt64<256, 2>,
                             cudaFuncAttributeMaxDynamicSharedMemorySize, SM);
        gemm_kt64<256, 2><<<128, 256, SM>>>(p_hmid, W_fc2, b_fc2, out, token, nullptr);
    }
}